// round 8
// baseline (speedup 1.0000x reference)
#include <cuda_runtime.h>
#include <cstdint>

// PatchGram, algebraically collapsed:
//   f[cr][p] = sum over K=C/64 consecutive channels of feat[n, cr*K+j, p]
//   g[d4][p] = sum over 4 consecutive cr rows of f
//   out[n,layer,c*16+d4] = f[c]·g[d4] / (36*K*K)
//
// Persistent CTAs, 2-deep TMA ring (R4-proven sync protocol), work-stealing
// with PREFETCHED work ids (ATOMG off the TMA-issue path). f/g rows padded
// to 12 floats so the 64x16 output dot uses LDS.128.

#define TILE_FLOATS (512 * 9)
#define TILE_BYTES  (TILE_FLOATS * 4)
#define NUM_CTAS    740
#define FPAD        12                  // padded row length (16B aligned)

__device__ int g_work;

struct __align__(16) Smem {
    float tile[2][TILE_FLOATS];         // 36864 B ring
    float f[64 * FPAD];                 // pooled features, padded rows
    float g[16 * FPAD];                 // 4-row group sums, padded rows
    unsigned long long mbar[2];
    int sq[2];                          // sample id per slot (-1 = sentinel)
    int pq[2];                          // pass id per slot
};

__device__ __forceinline__ uint32_t smem_u32(const void* p) {
    return (uint32_t)__cvta_generic_to_shared(p);
}

__device__ __forceinline__ void mbar_wait(uint32_t mbar, int parity) {
    asm volatile(
        "{\n\t"
        ".reg .pred P1;\n\t"
        "WAIT_%=:\n\t"
        "mbarrier.try_wait.parity.acquire.cta.shared::cta.b64 P1, [%0], %1, 0x989680;\n\t"
        "@P1 bra DONE_%=;\n\t"
        "bra WAIT_%=;\n\t"
        "DONE_%=:\n\t"
        "}"
        :: "r"(mbar), "r"(parity) : "memory");
}

// pool one 512-channel tile directly from smem (R4 path);
// thread owns channels (2*tid, 2*tid+1); G lanes per pool group.
template <int G>
__device__ __forceinline__ void pool_tile(const float* __restrict__ tile,
                                          float* __restrict__ f,
                                          int tid, int rowbase)
{
    float s[9];
    #pragma unroll
    for (int p = 0; p < 9; ++p) s[p] = 0.0f;

    // tile float offset 18*tid + 2k; 18*tid % 9 == 0 -> static rotation
    const float2* __restrict__ src = reinterpret_cast<const float2*>(tile) + tid * 9;
    #pragma unroll
    for (int k = 0; k < 9; ++k) {
        float2 v = src[k];
        s[(2 * k)     % 9] += v.x;
        s[(2 * k + 1) % 9] += v.y;
    }
    #pragma unroll
    for (int off = G / 2; off >= 1; off >>= 1) {
        #pragma unroll
        for (int p = 0; p < 9; ++p)
            s[p] += __shfl_down_sync(0xffffffffu, s[p], off);
    }
    if ((tid & (G - 1)) == 0) {
        const int cr = rowbase + tid / G;
        #pragma unroll
        for (int p = 0; p < 9; ++p)
            f[cr * FPAD + p] = s[p];
    }
}

// 9-term dot of two 12-float padded rows via float4 loads (tail unused)
__device__ __forceinline__ float dot9(const float4* __restrict__ A,
                                      const float4* __restrict__ B)
{
    float4 a0 = A[0], a1 = A[1], a2 = A[2];
    float4 b0 = B[0], b1 = B[1], b2 = B[2];
    float acc = a0.x * b0.x;
    acc = fmaf(a0.y, b0.y, acc);
    acc = fmaf(a0.z, b0.z, acc);
    acc = fmaf(a0.w, b0.w, acc);
    acc = fmaf(a1.x, b1.x, acc);
    acc = fmaf(a1.y, b1.y, acc);
    acc = fmaf(a1.z, b1.z, acc);
    acc = fmaf(a1.w, b1.w, acc);
    acc = fmaf(a2.x, b2.x, acc);
    return acc;
}

__global__ void reset_counter() { g_work = 0; }

__global__ __launch_bounds__(256)
void patch_gram_persistent(const float* __restrict__ feat0,
                           const float* __restrict__ feat1,
                           float* __restrict__ out,
                           int n0, int total)
{
    __shared__ Smem sm;
    const int tid = threadIdx.x;

    const uint32_t mb0 = smem_u32(&sm.mbar[0]);
    const uint32_t mb1 = smem_u32(&sm.mbar[1]);
    const uint32_t ts0 = smem_u32(sm.tile[0]);
    const uint32_t ts1 = smem_u32(sm.tile[1]);

    if (tid == 0) {
        asm volatile("mbarrier.init.shared.b64 [%0], 1;" :: "r"(mb0) : "memory");
        asm volatile("mbarrier.init.shared.b64 [%0], 1;" :: "r"(mb1) : "memory");
    }
    __syncthreads();

    // ---- tid0-only issue state (work id prefetched one sample ahead) ----
    int cur = 0, pass = 0, np = 0, nxt = 0;
    if (tid == 0) {
        cur = atomicAdd(&g_work, 1);
        np  = (cur < n0) ? 1 : 2;
        nxt = atomicAdd(&g_work, 1);    // resolves while first tile streams
    }

    auto issue = [&](int b) {           // tid==0 only
        const uint32_t mb = b ? mb1 : mb0;
        if (cur >= total) {             // out of work: sentinel arrive
            sm.sq[b] = -1;
            asm volatile("mbarrier.arrive.shared.b64 _, [%0];" :: "r"(mb) : "memory");
            return;
        }
        sm.sq[b] = cur;
        sm.pq[b] = pass;
        const char* src = (cur < n0)
            ? (const char*)(feat0 + (size_t)cur * TILE_FLOATS)
            : (const char*)(feat1 + (size_t)(cur - n0) * (2 * TILE_FLOATS) + (size_t)pass * TILE_FLOATS);
        asm volatile("mbarrier.arrive.expect_tx.shared.b64 _, [%0], %1;"
                     :: "r"(mb), "n"(TILE_BYTES) : "memory");
        asm volatile("cp.async.bulk.shared::cta.global.mbarrier::complete_tx::bytes"
                     " [%0], [%1], %2, [%3];"
                     :: "r"(b ? ts1 : ts0), "l"(src), "n"(TILE_BYTES), "r"(mb)
                     : "memory");
        if (++pass >= np) {             // advance to prefetched sample
            cur  = nxt;
            pass = 0;
            np   = (cur < n0) ? 1 : 2;
            nxt  = atomicAdd(&g_work, 1);   // latency hidden behind this tile
        }
    };

    if (tid == 0) { issue(0); issue(1); }

    // ---- consume loop (R4 structure, all threads lockstep) ----
    int consumed = 0;
    while (true) {
        const int b   = consumed & 1;
        const int par = (consumed >> 1) & 1;
        mbar_wait(b ? mb1 : mb0, par);

        const int s = sm.sq[b];
        if (s < 0) break;
        const int ph    = sm.pq[b];
        const bool is_l0 = (s < n0);

        if (is_l0) pool_tile<4>(sm.tile[b], sm.f, tid, 0);        // K=8:  64 rows
        else       pool_tile<8>(sm.tile[b], sm.f, tid, ph * 32);  // K=16: 32 rows/pass
        __syncthreads();                  // tile consumed + f rows visible

        if (tid == 0) issue(b);           // refill freed slot; overlaps epilogue

        const bool last = is_l0 || (ph == 1);
        if (last) {
            // stage 3: 4-row group sums
            if (tid < 144) {              // tid = d4*9 + p
                const int d4 = tid / 9;
                const int p  = tid - d4 * 9;
                const float* bp = sm.f + (4 * d4) * FPAD + p;
                sm.g[d4 * FPAD + p] = bp[0] + bp[FPAD] + bp[2 * FPAD] + bp[3 * FPAD];
            }
            __syncthreads();

            // stage 4: 64x16 dot, 2x2 register blocking, LDS.128 reads
            {
                const int n     = is_l0 ? s : (s - n0);
                const int layer = is_l0 ? 0 : 1;
                const float scale = is_l0 ? (1.0f / (36.0f * 64.0f))
                                          : (1.0f / (36.0f * 256.0f));
                float* __restrict__ dst = out + ((size_t)n * 2 + layer) * 1024;

                const int c  = (tid >> 3) * 2;
                const int d4 = (tid & 7) * 2;
                const float4* __restrict__ F0 =
                    reinterpret_cast<const float4*>(sm.f + c * FPAD);
                const float4* __restrict__ F1 =
                    reinterpret_cast<const float4*>(sm.f + (c + 1) * FPAD);
                const float4* __restrict__ G0 =
                    reinterpret_cast<const float4*>(sm.g + d4 * FPAD);
                const float4* __restrict__ G1 =
                    reinterpret_cast<const float4*>(sm.g + (d4 + 1) * FPAD);

                const float a00 = dot9(F0, G0), a01 = dot9(F0, G1);
                const float a10 = dot9(F1, G0), a11 = dot9(F1, G1);

                float2* __restrict__ d2 = reinterpret_cast<float2*>(dst);
                d2[(c * 16 + d4) >> 1]       = make_float2(a00 * scale, a01 * scale);
                d2[((c + 1) * 16 + d4) >> 1] = make_float2(a10 * scale, a11 * scale);
            }
            __syncthreads();              // protect f/g before next pooling
        }
        ++consumed;
    }
}

extern "C" void kernel_launch(void* const* d_in, const int* in_sizes, int n_in,
                              void* d_out, int out_size)
{
    const float* feat0 = (const float*)d_in[0];   // [6272, 512, 3, 3]
    const float* feat1 = (const float*)d_in[1];   // [6272, 1024, 3, 3]
    float* out = (float*)d_out;                   // [6272, 2, 1024]

    const int N0 = in_sizes[0] / (512 * 9);
    const int N1 = in_sizes[1] / (1024 * 9);
    const int total = N0 + N1;

    reset_counter<<<1, 1>>>();
    const int grid = total < NUM_CTAS ? total : NUM_CTAS;
    patch_gram_persistent<<<grid, 256>>>(feat0, feat1, out, N0, total);
}